// round 2
// baseline (speedup 1.0000x reference)
#include <cuda_runtime.h>
#include <cuda_bf16.h>

#define NFIELD 39
#define EMB    16
#define VOCAB  200000
#define NFE    624      // 39*16
#define ND     64
#define BATCH  16384

// Re-packed weights: for fe in [0,624), dg in [0,4), 16 floats:
//   [2j]   = W1[dg*8+j][fe]
//   [2j+1] = Wi[dg*8+j][fe]      (j = 0..7)
// so one fma.rn.f32x2 accumulates (first_order_d, s_d) together.
__device__ float WtG[NFE * ND];

__global__ void prep_kernel(const float* __restrict__ W1, const float* __restrict__ Wi) {
    int i = blockIdx.x * blockDim.x + threadIdx.x;
    if (i >= NFE * ND) return;
    int fe = i >> 6;
    int r  = i & 63;
    int dg = r >> 4;
    int q  = r & 15;
    int j  = q >> 1;
    int p  = q & 1;
    int d  = dg * 8 + j;
    WtG[i] = (p == 0) ? W1[d * NFE + fe] : Wi[d * NFE + fe];
}

__device__ __forceinline__ unsigned long long pack2(float v) {
    unsigned long long r;
    asm("mov.b64 %0, {%1, %2};" : "=l"(r) : "f"(v), "f"(v));
    return r;
}
__device__ __forceinline__ unsigned long long fma2(unsigned long long a, unsigned long long b,
                                                   unsigned long long c) {
    unsigned long long d;
    asm("fma.rn.f32x2 %0, %1, %2, %3;" : "=l"(d) : "l"(a), "l"(b), "l"(c));
    return d;
}
__device__ __forceinline__ void unpack2(unsigned long long v, float& lo, float& hi) {
    asm("mov.b64 {%0, %1}, %2;" : "=f"(lo), "=f"(hi) : "l"(v));
}

// Shared layout (floats):
//   sW   [0, 39936)       Wt (full)                 159744 B
//   sXv  [39936, 44928)   Xv for 128 rows  (aliased by sX after GEMM)
//   sXi  [44928, 49920)   Xi for 128 rows  (aliased by sH after GEMM)
//   sM   [49920, 52065)   MLP weights
#define SW_OFF  0
#define SXV_OFF 39936
#define SXI_OFF 44928
#define SM_OFF  49920
#define SMEM_FLOATS (SM_OFF + 2145)
#define SMEM_BYTES  (SMEM_FLOATS * 4)

#define ROWS_PER_BLOCK 128
#define THREADS 512
#define XPITCH 33   // padded row pitch for x/h exchange (conflict-free)

__global__ __launch_bounds__(THREADS, 1)
void pnn_kernel(const int*   __restrict__ Xi,
                const float* __restrict__ Xv,
                const float* __restrict__ tables,
                const float* __restrict__ lin1_w,
                const float* __restrict__ lin1_b,
                const float* __restrict__ lin2_w,
                const float* __restrict__ lin2_b,
                const float* __restrict__ last_w,
                const float* __restrict__ last_b,
                float*       __restrict__ out) {
    extern __shared__ float smem[];
    float* sW  = smem + SW_OFF;
    float* sXv = smem + SXV_OFF;
    int*   sXi = (int*)(smem + SXI_OFF);
    float* sM  = smem + SM_OFF;

    const int tid = threadIdx.x;
    const int dg  = tid >> 7;        // d-group 0..3  -> outputs d in [dg*8, dg*8+8)
    const int row = tid & 127;       // row within block
    const int b0  = blockIdx.x * ROWS_PER_BLOCK;

    // ---- stage W ----
    {
        const float4* src = (const float4*)WtG;
        float4* dst = (float4*)sW;
        #pragma unroll 4
        for (int i = tid; i < NFE * ND / 4; i += THREADS) dst[i] = src[i];
    }
    // ---- stage Xi/Xv ----
    {
        const float4* srcv = (const float4*)(Xv + (size_t)b0 * NFIELD);
        float4* dstv = (float4*)sXv;
        const int4* srci = (const int4*)(Xi + (size_t)b0 * NFIELD);
        int4* dsti = (int4*)sXi;
        for (int i = tid; i < ROWS_PER_BLOCK * NFIELD / 4; i += THREADS) {
            dstv[i] = srcv[i];
            dsti[i] = srci[i];
        }
    }
    // ---- stage MLP weights ----
    for (int i = tid; i < 1024; i += THREADS) {
        sM[i]        = lin1_w[i];
        sM[1056 + i] = lin2_w[i];
    }
    if (tid < 32) {
        sM[1024 + tid] = lin1_b[tid];
        sM[2080 + tid] = lin2_b[tid];
        sM[2112 + tid] = last_w[tid];
    }
    if (tid == 0) sM[2144] = last_b[0];
    __syncthreads();

    // ---- GEMM slice: this thread accumulates 8 (fo, s) pairs for its row ----
    unsigned long long acc[8];
    #pragma unroll
    for (int k = 0; k < 8; ++k) acc[k] = 0ull;

    const int myoff = row * NFIELD;

    float xv = sXv[myoff];
    int   idx = sXi[myoff];
    const float4* rp = (const float4*)tables + ((long)idx) * 4;
    float4 c0 = rp[0], c1 = rp[1], c2 = rp[2], c3 = rp[3];

    #pragma unroll 1
    for (int f = 0; f < NFIELD; ++f) {
        float4 n0, n1, n2, n3;
        float nxv = 0.f;
        if (f < NFIELD - 1) {
            int nidx = sXi[myoff + f + 1];
            nxv = sXv[myoff + f + 1];
            const float4* np = (const float4*)tables + ((long)(f + 1) * VOCAB + nidx) * 4;
            n0 = np[0]; n1 = np[1]; n2 = np[2]; n3 = np[3];
        } else {
            n0 = c0; n1 = c1; n2 = c2; n3 = c3;
        }

        float ev[16] = {c0.x * xv, c0.y * xv, c0.z * xv, c0.w * xv,
                        c1.x * xv, c1.y * xv, c1.z * xv, c1.w * xv,
                        c2.x * xv, c2.y * xv, c2.z * xv, c2.w * xv,
                        c3.x * xv, c3.y * xv, c3.z * xv, c3.w * xv};

        const float* wbase = sW + ((size_t)f * EMB * 4 + dg) * 16;
        #pragma unroll
        for (int ee = 0; ee < EMB; ++ee) {
            unsigned long long v2 = pack2(ev[ee]);
            const ulonglong2* wp = (const ulonglong2*)(wbase + ee * ND);
            #pragma unroll
            for (int j2 = 0; j2 < 4; ++j2) {
                ulonglong2 w = wp[j2];                 // broadcast LDS.128
                acc[2 * j2]     = fma2(w.x, v2, acc[2 * j2]);
                acc[2 * j2 + 1] = fma2(w.y, v2, acc[2 * j2 + 1]);
            }
        }

        c0 = n0; c1 = n1; c2 = n2; c3 = n3; xv = nxv;
    }

    // ---- combine: x_d = fo_d + s_d^2 for this thread's 8 d's ----
    float xo[8];
    #pragma unroll
    for (int j = 0; j < 8; ++j) {
        float fo, s;
        unpack2(acc[j], fo, s);
        xo[j] = fmaf(s, s, fo);
    }

    // exchange buffers alias the (now dead) Xi/Xv staging area
    float* sX = smem + SXV_OFF;                    // 128 * 33 floats
    float* sH = smem + SXV_OFF + ROWS_PER_BLOCK * XPITCH;

    __syncthreads();   // everyone done reading sXv/sXi
    #pragma unroll
    for (int j = 0; j < 8; ++j) sX[row * XPITCH + dg * 8 + j] = xo[j];
    __syncthreads();

    // ---- layer 1 (each thread: 8 of 32 outputs for its row) ----
    float xr[32];
    #pragma unroll
    for (int j = 0; j < 32; ++j) xr[j] = sX[row * XPITCH + j];
    #pragma unroll
    for (int i = 0; i < 8; ++i) {
        int oi = dg * 8 + i;
        float t = sM[1024 + oi];
        #pragma unroll
        for (int j4 = 0; j4 < 8; ++j4) {
            float4 w = *(const float4*)&sM[oi * 32 + j4 * 4];
            t = fmaf(xr[j4 * 4],     w.x, t);
            t = fmaf(xr[j4 * 4 + 1], w.y, t);
            t = fmaf(xr[j4 * 4 + 2], w.z, t);
            t = fmaf(xr[j4 * 4 + 3], w.w, t);
        }
        sH[row * XPITCH + oi] = fmaxf(t, 0.f);
    }
    __syncthreads();

    // ---- layer 2 ----
    float hr[32];
    #pragma unroll
    for (int j = 0; j < 32; ++j) hr[j] = sH[row * XPITCH + j];
    #pragma unroll
    for (int i = 0; i < 8; ++i) {
        int oi = dg * 8 + i;
        float t = sM[2080 + oi];
        #pragma unroll
        for (int j4 = 0; j4 < 8; ++j4) {
            float4 w = *(const float4*)&sM[1056 + oi * 32 + j4 * 4];
            t = fmaf(hr[j4 * 4],     w.x, t);
            t = fmaf(hr[j4 * 4 + 1], w.y, t);
            t = fmaf(hr[j4 * 4 + 2], w.z, t);
            t = fmaf(hr[j4 * 4 + 3], w.w, t);
        }
        sX[row * XPITCH + oi] = fmaxf(t, 0.f);   // reuse sX for h2
    }
    __syncthreads();

    // ---- final layer: one thread per row ----
    if (dg == 0) {
        float o = sM[2144];
        #pragma unroll
        for (int j = 0; j < 32; ++j) o = fmaf(sX[row * XPITCH + j], sM[2112 + j], o);
        out[b0 + row] = o;
    }
}

extern "C" void kernel_launch(void* const* d_in, const int* in_sizes, int n_in,
                              void* d_out, int out_size) {
    const int*   Xi     = (const int*)  d_in[0];
    const float* Xv     = (const float*)d_in[1];
    const float* tables = (const float*)d_in[2];
    const float* W1     = (const float*)d_in[3];
    const float* Wi     = (const float*)d_in[4];
    const float* lin1_w = (const float*)d_in[5];
    const float* lin1_b = (const float*)d_in[6];
    const float* lin2_w = (const float*)d_in[7];
    const float* lin2_b = (const float*)d_in[8];
    const float* last_w = (const float*)d_in[9];
    const float* last_b = (const float*)d_in[10];
    float* out = (float*)d_out;

    static bool attr_set = false;
    if (!attr_set) {
        cudaFuncSetAttribute(pnn_kernel, cudaFuncAttributeMaxDynamicSharedMemorySize, SMEM_BYTES);
        attr_set = true;
    }

    prep_kernel<<<(NFE * ND + 255) / 256, 256>>>(W1, Wi);
    pnn_kernel<<<BATCH / ROWS_PER_BLOCK, THREADS, SMEM_BYTES>>>(
        Xi, Xv, tables, lin1_w, lin1_b, lin2_w, lin2_b, last_w, last_b, out);
}

// round 3
// speedup vs baseline: 1.0621x; 1.0621x over previous
#include <cuda_runtime.h>
#include <cuda_bf16.h>

#define NFIELD 39
#define EMB    16
#define VOCAB  200000
#define NFE    624      // 39*16
#define ND     64
#define BATCH  16384

// Packed weights: Wt[fe][64], pair p (0..31): [2p]=W1[p][fe], [2p+1]=Wi[p][fe]
// so one fma.rn.f32x2 accumulates (first_order_d, s_d) together for d=p.
__device__ float WtG[NFE * ND];

__global__ void prep_kernel(const float* __restrict__ W1, const float* __restrict__ Wi) {
    int i = blockIdx.x * blockDim.x + threadIdx.x;
    if (i >= NFE * ND) return;
    int fe = i >> 6;
    int r  = i & 63;
    int d  = r >> 1;
    int p  = r & 1;
    WtG[i] = (p == 0) ? W1[d * NFE + fe] : Wi[d * NFE + fe];
}

__device__ __forceinline__ unsigned long long fma2(unsigned long long a, unsigned long long b,
                                                   unsigned long long c) {
    unsigned long long d;
    asm("fma.rn.f32x2 %0, %1, %2, %3;" : "=l"(d) : "l"(a), "l"(b), "l"(c));
    return d;
}
__device__ __forceinline__ void unpack2(unsigned long long v, float& lo, float& hi) {
    asm("mov.b64 {%0, %1}, %2;" : "=f"(lo), "=f"(hi) : "l"(v));
}

// Shared layout (floats):
//   sW  [0, 39936)          Wt (full)        159744 B   (aliased by sX/sH/sX2 after GEMM)
//   sE  [39936, 48128)      E tiles, 2 bufs x 16k x 128row x float2 (dup)  32768 B
//   sM  [48128, 50273)      MLP weights       8580 B
#define SW_OFF  0
#define SE_OFF  39936
#define SM_OFF  48128
#define SMEM_FLOATS (SM_OFF + 2145)
#define SMEM_BYTES  (SMEM_FLOATS * 4)

#define ROWS_PER_BLOCK 128
#define THREADS 256
#define XPITCH 33

__global__ __launch_bounds__(THREADS, 1)
void pnn_kernel(const int*   __restrict__ Xi,
                const float* __restrict__ Xv,
                const float* __restrict__ tables,
                const float* __restrict__ lin1_w,
                const float* __restrict__ lin1_b,
                const float* __restrict__ lin2_w,
                const float* __restrict__ lin2_b,
                const float* __restrict__ last_w,
                const float* __restrict__ last_b,
                float*       __restrict__ out) {
    extern __shared__ float smem[];
    float* sW = smem + SW_OFF;
    float* sE = smem + SE_OFF;   // [buf][k][row] float2 (value duplicated)
    float* sM = smem + SM_OFF;

    const int tid = threadIdx.x;
    const int b0  = blockIdx.x * ROWS_PER_BLOCK;

    // GEMM tile mapping: 32 row-blocks x 8 pair-blocks
    const int rb = tid & 31;         // row block   -> rows [rb*4, rb*4+4)
    const int pb = tid >> 5;         // pair block  -> pairs [pb*4, pb*4+4)
    const int r0 = rb * 4;
    const int p0 = pb * 4;

    // gather mapping: 2 threads per row
    const int gr = tid >> 1;         // row 0..127
    const int gh = tid & 1;          // half: k in [gh*8, gh*8+8)

    // ---- stage W (full 160KB) ----
    {
        const float4* src = (const float4*)WtG;
        float4* dst = (float4*)sW;
        #pragma unroll 4
        for (int i = tid; i < NFE * ND / 4; i += THREADS) dst[i] = src[i];
    }
    // ---- stage MLP weights ----
    for (int i = tid; i < 1024; i += THREADS) {
        sM[i]        = lin1_w[i];
        sM[1056 + i] = lin2_w[i];
    }
    if (tid < 32) {
        sM[1024 + tid] = lin1_b[tid];
        sM[2080 + tid] = lin2_b[tid];
        sM[2112 + tid] = last_w[tid];
    }
    if (tid == 0) sM[2144] = last_b[0];

    // ---- prologue: gather field 0 into buf 0 ----
    {
        int   idx = Xi[(size_t)(b0 + gr) * NFIELD];
        float xv  = Xv[(size_t)(b0 + gr) * NFIELD];
        const float4* rp = (const float4*)tables + ((long)idx) * 4 + gh * 2;
        float4 ta = rp[0], tb = rp[1];
        float* db = sE + gr * 2;                 // buf 0
        float2* d0 = (float2*)(db + (gh * 8 + 0) * 256);
        float v;
        v = ta.x * xv; *(float2*)(db + (gh*8+0)*256) = make_float2(v, v);
        v = ta.y * xv; *(float2*)(db + (gh*8+1)*256) = make_float2(v, v);
        v = ta.z * xv; *(float2*)(db + (gh*8+2)*256) = make_float2(v, v);
        v = ta.w * xv; *(float2*)(db + (gh*8+3)*256) = make_float2(v, v);
        v = tb.x * xv; *(float2*)(db + (gh*8+4)*256) = make_float2(v, v);
        v = tb.y * xv; *(float2*)(db + (gh*8+5)*256) = make_float2(v, v);
        v = tb.z * xv; *(float2*)(db + (gh*8+6)*256) = make_float2(v, v);
        v = tb.w * xv; *(float2*)(db + (gh*8+7)*256) = make_float2(v, v);
        (void)d0;
    }
    __syncthreads();

    // ---- main loop: double-buffered gather + register-tiled GEMM ----
    unsigned long long acc[16];      // [ri*4+pi] = (fo, s) for (row r0+ri, d p0+pi)
    #pragma unroll
    for (int k = 0; k < 16; ++k) acc[k] = 0ull;

    #pragma unroll 1
    for (int f = 0; f < NFIELD; ++f) {
        const int buf = f & 1;

        // prefetch gather for f+1 (LDG latency hidden behind compute below)
        float4 na, nb;
        float nxv = 0.f;
        if (f + 1 < NFIELD) {
            int nidx = Xi[(size_t)(b0 + gr) * NFIELD + f + 1];
            nxv = Xv[(size_t)(b0 + gr) * NFIELD + f + 1];
            const float4* np = (const float4*)tables + ((long)(f + 1) * VOCAB + nidx) * 4 + gh * 2;
            na = np[0]; nb = np[1];
        }

        // GEMM: 16 k-steps, per step 4 LDS.128 -> 16 fma2
        const float* eb = sE + buf * 4096 + r0 * 2;
        const float* wb = sW + (size_t)f * 16 * 64 + p0 * 2;
        #pragma unroll
        for (int k = 0; k < 16; ++k) {
            ulonglong2 e01 = *(const ulonglong2*)(eb + k * 256);
            ulonglong2 e23 = *(const ulonglong2*)(eb + k * 256 + 4);
            ulonglong2 w01 = *(const ulonglong2*)(wb + k * 64);
            ulonglong2 w23 = *(const ulonglong2*)(wb + k * 64 + 4);
            unsigned long long e[4] = {e01.x, e01.y, e23.x, e23.y};
            unsigned long long w[4] = {w01.x, w01.y, w23.x, w23.y};
            #pragma unroll
            for (int ri = 0; ri < 4; ++ri)
                #pragma unroll
                for (int pi = 0; pi < 4; ++pi)
                    acc[ri * 4 + pi] = fma2(e[ri], w[pi], acc[ri * 4 + pi]);
        }

        // store gathered f+1 into the other buffer
        if (f + 1 < NFIELD) {
            float* db = sE + (buf ^ 1) * 4096 + gr * 2;
            float v;
            v = na.x * nxv; *(float2*)(db + (gh*8+0)*256) = make_float2(v, v);
            v = na.y * nxv; *(float2*)(db + (gh*8+1)*256) = make_float2(v, v);
            v = na.z * nxv; *(float2*)(db + (gh*8+2)*256) = make_float2(v, v);
            v = na.w * nxv; *(float2*)(db + (gh*8+3)*256) = make_float2(v, v);
            v = nb.x * nxv; *(float2*)(db + (gh*8+4)*256) = make_float2(v, v);
            v = nb.y * nxv; *(float2*)(db + (gh*8+5)*256) = make_float2(v, v);
            v = nb.z * nxv; *(float2*)(db + (gh*8+6)*256) = make_float2(v, v);
            v = nb.w * nxv; *(float2*)(db + (gh*8+7)*256) = make_float2(v, v);
        }
        __syncthreads();
    }

    // ---- combine fo + s^2, write x into sX (aliases dead sW region) ----
    float* sX  = smem;               // 128 x 33
    float* sH  = smem + 4224;        // 128 x 33
    float* sX2 = smem + 8448;        // 128 x 33
    #pragma unroll
    for (int ri = 0; ri < 4; ++ri)
        #pragma unroll
        for (int pi = 0; pi < 4; ++pi) {
            float fo, s;
            unpack2(acc[ri * 4 + pi], fo, s);
            sX[(r0 + ri) * XPITCH + p0 + pi] = fmaf(s, s, fo);
        }
    __syncthreads();

    // ---- MLP: 2 threads per row, each computes 16 of 32 outputs/layer ----
    const int row = gr;
    const int hh  = gh;

    float xr[32];
    #pragma unroll
    for (int j = 0; j < 32; ++j) xr[j] = sX[row * XPITCH + j];
    #pragma unroll
    for (int i = 0; i < 16; ++i) {
        int oi = hh * 16 + i;
        float t = sM[1024 + oi];
        #pragma unroll
        for (int j4 = 0; j4 < 8; ++j4) {
            float4 w = *(const float4*)&sM[oi * 32 + j4 * 4];
            t = fmaf(xr[j4 * 4],     w.x, t);
            t = fmaf(xr[j4 * 4 + 1], w.y, t);
            t = fmaf(xr[j4 * 4 + 2], w.z, t);
            t = fmaf(xr[j4 * 4 + 3], w.w, t);
        }
        sH[row * XPITCH + oi] = fmaxf(t, 0.f);
    }
    __syncthreads();

    float hr[32];
    #pragma unroll
    for (int j = 0; j < 32; ++j) hr[j] = sH[row * XPITCH + j];
    #pragma unroll
    for (int i = 0; i < 16; ++i) {
        int oi = hh * 16 + i;
        float t = sM[2080 + oi];
        #pragma unroll
        for (int j4 = 0; j4 < 8; ++j4) {
            float4 w = *(const float4*)&sM[1056 + oi * 32 + j4 * 4];
            t = fmaf(hr[j4 * 4],     w.x, t);
            t = fmaf(hr[j4 * 4 + 1], w.y, t);
            t = fmaf(hr[j4 * 4 + 2], w.z, t);
            t = fmaf(hr[j4 * 4 + 3], w.w, t);
        }
        sX2[row * XPITCH + oi] = fmaxf(t, 0.f);
    }
    __syncthreads();

    if (hh == 0) {
        float o = sM[2144];
        #pragma unroll
        for (int j = 0; j < 32; ++j) o = fmaf(sX2[row * XPITCH + j], sM[2112 + j], o);
        out[b0 + row] = o;
    }
}

extern "C" void kernel_launch(void* const* d_in, const int* in_sizes, int n_in,
                              void* d_out, int out_size) {
    const int*   Xi     = (const int*)  d_in[0];
    const float* Xv     = (const float*)d_in[1];
    const float* tables = (const float*)d_in[2];
    const float* W1     = (const float*)d_in[3];
    const float* Wi     = (const float*)d_in[4];
    const float* lin1_w = (const float*)d_in[5];
    const float* lin1_b = (const float*)d_in[6];
    const float* lin2_w = (const float*)d_in[7];
    const float* lin2_b = (const float*)d_in[8];
    const float* last_w = (const float*)d_in[9];
    const float* last_b = (const float*)d_in[10];
    float* out = (float*)d_out;

    static bool attr_set = false;
    if (!attr_set) {
        cudaFuncSetAttribute(pnn_kernel, cudaFuncAttributeMaxDynamicSharedMemorySize, SMEM_BYTES);
        attr_set = true;
    }

    prep_kernel<<<(NFE * ND + 255) / 256, 256>>>(W1, Wi);
    pnn_kernel<<<BATCH / ROWS_PER_BLOCK, THREADS, SMEM_BYTES>>>(
        Xi, Xv, tables, lin1_w, lin1_b, lin2_w, lin2_b, last_w, last_b, out);
}

// round 5
// speedup vs baseline: 1.5175x; 1.4287x over previous
#include <cuda_runtime.h>
#include <cuda_bf16.h>
#include <cstdint>

#define NFIELD 39
#define VOCAB  200000
#define BATCH  16384
#define ROWSPB 128
#define THREADS 256
#define NKSTEP 40          // 640 padded k / 16

// B fragments, m16n8k16 per-lane layout:
// [hl(2)][kstep(40)][ntile(8)][lane(32)][reg(2)] uint32 (bf16x2) = 160KB
__device__ __align__(16) uint32_t BfragG[2 * 40 * 8 * 32 * 2];

__global__ void prep_kernel(const float* __restrict__ W1, const float* __restrict__ Wi) {
    int i = blockIdx.x * blockDim.x + threadIdx.x;
    if (i >= 2 * 40 * 8 * 32 * 2) return;
    int reg = i & 1;
    int l   = (i >> 1) & 31;
    int t   = (i >> 6) & 7;
    int s   = (i >> 9) % 40;
    int hl  = (i >> 9) / 40;
    int n  = t * 8 + (l >> 2);
    int k0 = s * 16 + (l & 3) * 2 + reg * 8;
    float v0 = 0.f, v1 = 0.f;
    if (k0 < 624)     v0 = (n < 32) ? W1[n * 624 + k0]       : Wi[(n - 32) * 624 + k0];
    if (k0 + 1 < 624) v1 = (n < 32) ? W1[n * 624 + k0 + 1]   : Wi[(n - 32) * 624 + k0 + 1];
    float h0 = __bfloat162float(__float2bfloat16(v0));
    float h1 = __bfloat162float(__float2bfloat16(v1));
    uint32_t word;
    if (hl == 0) {  // hi parts: low half = k even elem
        asm("cvt.rn.bf16x2.f32 %0, %1, %2;" : "=r"(word) : "f"(h1), "f"(h0));
    } else {        // residuals
        float r0 = v0 - h0, r1 = v1 - h1;
        asm("cvt.rn.bf16x2.f32 %0, %1, %2;" : "=r"(word) : "f"(r1), "f"(r0));
    }
    BfragG[i] = word;
}

__device__ __forceinline__ uint32_t packbf(float lo_elem, float hi_elem) {
    uint32_t r;
    asm("cvt.rn.bf16x2.f32 %0, %1, %2;" : "=r"(r) : "f"(hi_elem), "f"(lo_elem));
    return r;
}

__device__ __forceinline__ void mma16816(float* d, uint32_t a0, uint32_t a1, uint32_t a2, uint32_t a3,
                                         uint32_t b0, uint32_t b1) {
    asm volatile("mma.sync.aligned.m16n8k16.row.col.f32.bf16.bf16.f32 "
                 "{%0,%1,%2,%3}, {%4,%5,%6,%7}, {%8,%9}, {%0,%1,%2,%3};"
                 : "+f"(d[0]), "+f"(d[1]), "+f"(d[2]), "+f"(d[3])
                 : "r"(a0), "r"(a1), "r"(a2), "r"(a3), "r"(b0), "r"(b1));
}

// smem layout (bytes):
//   A frags [hl2][warp8][kstep8][lane32][16B]  @ 0,     65536 B (reused by epilogue)
//   B frags [hl2][gs40][t8][lane32][8B]        @ 65536, 163840 B
#define OFF_A 0
#define OFF_B 65536
#define SMEM_BYTES (65536 + 163840)
// epilogue aliases inside A region:
#define EXP_X  0        // 128 x 33 floats
#define EXP_H  16896    // 128 x 33 floats
#define EXP_M  33792    // 2145 floats

__global__ __launch_bounds__(THREADS, 1)
void pnn_kernel(const int*   __restrict__ Xi,
                const float* __restrict__ Xv,
                const float* __restrict__ tables,
                const float* __restrict__ lin1_w,
                const float* __restrict__ lin1_b,
                const float* __restrict__ lin2_w,
                const float* __restrict__ lin2_b,
                const float* __restrict__ last_w,
                const float* __restrict__ last_b,
                float*       __restrict__ out) {
    extern __shared__ unsigned char smem[];

    const int tid = threadIdx.x;
    const int wid = tid >> 5;
    const int l   = tid & 31;
    const int b0  = blockIdx.x * ROWSPB;

    // gather mapping: 2 threads per row
    const int grow = tid >> 1;       // 0..127
    const int gh   = tid & 1;
    const int gw   = grow >> 4;      // which warp-slab this row belongs to
    const int gm   = grow & 15;      // row within slab
    const int glane4 = (gm & 7) * 4; // lane group base
    const int gregoff = (gm >= 8) ? 8 : 0;

    // ---- stage B fragments (160KB, coalesced) ----
    {
        const uint4* src = (const uint4*)BfragG;
        uint4* dst = (uint4*)(smem + OFF_B);
        #pragma unroll 4
        for (int i = tid; i < 163840 / 16; i += THREADS) dst[i] = src[i];
    }

    float acc[8][4];
    #pragma unroll
    for (int t = 0; t < 8; ++t)
        #pragma unroll
        for (int r = 0; r < 4; ++r) acc[t][r] = 0.f;

    // ---- 5 k-chunks of 128 k (8 fields each) ----
    #pragma unroll 1
    for (int c = 0; c < 5; ++c) {
        // gather + convert 4 fields per thread into A fragment layout
        #pragma unroll
        for (int j = 0; j < 4; ++j) {
            const int f = c * 8 + gh * 4 + j;   // field == kstep within 640-k space
            const int s = gh * 4 + j;           // kstep within chunk
            unsigned char* abase_h = smem + OFF_A + ((((0 * 8 + gw) * 8 + s) * 32) * 16);
            unsigned char* abase_l = smem + OFF_A + ((((1 * 8 + gw) * 8 + s) * 32) * 16);
            if (f < NFIELD) {
                int   idx = Xi[(size_t)(b0 + grow) * NFIELD + f];
                float xv  = Xv[(size_t)(b0 + grow) * NFIELD + f];
                const float4* rp = (const float4*)tables + ((long)f * VOCAB + idx) * 4;
                float4 t0 = rp[0], t1 = rp[1], t2 = rp[2], t3 = rp[3];
                float v[16] = {t0.x * xv, t0.y * xv, t0.z * xv, t0.w * xv,
                               t1.x * xv, t1.y * xv, t1.z * xv, t1.w * xv,
                               t2.x * xv, t2.y * xv, t2.z * xv, t2.w * xv,
                               t3.x * xv, t3.y * xv, t3.z * xv, t3.w * xv};
                float hi[16], rs[16];
                #pragma unroll
                for (int e = 0; e < 16; ++e) {
                    hi[e] = __bfloat162float(__float2bfloat16(v[e]));
                    rs[e] = v[e] - hi[e];
                }
                #pragma unroll
                for (int q = 0; q < 4; ++q) {
                    uint32_t a0h = packbf(v[2 * q],     v[2 * q + 1]);      // k 2q,2q+1 (hi = rn of v)
                    uint32_t a2h = packbf(v[8 + 2 * q], v[9 + 2 * q]);
                    uint32_t a0l = packbf(rs[2 * q],     rs[2 * q + 1]);
                    uint32_t a2l = packbf(rs[8 + 2 * q], rs[9 + 2 * q]);
                    *(uint2*)(abase_h + (glane4 + q) * 16 + gregoff) = make_uint2(a0h, a2h);
                    *(uint2*)(abase_l + (glane4 + q) * 16 + gregoff) = make_uint2(a0l, a2l);
                }
            } else {
                #pragma unroll
                for (int q = 0; q < 4; ++q) {
                    *(uint2*)(abase_h + (glane4 + q) * 16 + gregoff) = make_uint2(0u, 0u);
                    *(uint2*)(abase_l + (glane4 + q) * 16 + gregoff) = make_uint2(0u, 0u);
                }
            }
        }
        __syncthreads();

        // GEMM on this chunk
        #pragma unroll
        for (int s = 0; s < 8; ++s) {
            const int gs = c * 8 + s;
            uint4 Ah = *(const uint4*)(smem + OFF_A + (((0 * 8 + wid) * 8 + s) * 32 + l) * 16);
            uint4 Al = *(const uint4*)(smem + OFF_A + (((1 * 8 + wid) * 8 + s) * 32 + l) * 16);
            // stored order [a0,a2,a1,a3]: a0=x, a1=z, a2=y, a3=w
            #pragma unroll
            for (int t = 0; t < 8; ++t) {
                uint2 Bh = *(const uint2*)(smem + OFF_B + (((0 * 40 + gs) * 8 + t) * 32 + l) * 8);
                uint2 Bl = *(const uint2*)(smem + OFF_B + (((1 * 40 + gs) * 8 + t) * 32 + l) * 8);
                mma16816(acc[t], Ah.x, Ah.z, Ah.y, Ah.w, Bh.x, Bh.y);
                mma16816(acc[t], Ah.x, Ah.z, Ah.y, Ah.w, Bl.x, Bl.y);
                mma16816(acc[t], Al.x, Al.z, Al.y, Al.w, Bh.x, Bh.y);
            }
        }
        __syncthreads();
    }

    // ---- epilogue: x = fo + s^2 from D frags; exchange via smem ----
    float* sX = (float*)(smem + EXP_X);
    float* sH = (float*)(smem + EXP_H);
    float* sM = (float*)(smem + EXP_M);

    {
        const int r0 = wid * 16 + (l >> 2);
        const int r1 = r0 + 8;
        #pragma unroll
        for (int t = 0; t < 4; ++t) {
            const int c0 = t * 8 + (l & 3) * 2;
            sX[r0 * 33 + c0]     = fmaf(acc[t + 4][0], acc[t + 4][0], acc[t][0]);
            sX[r0 * 33 + c0 + 1] = fmaf(acc[t + 4][1], acc[t + 4][1], acc[t][1]);
            sX[r1 * 33 + c0]     = fmaf(acc[t + 4][2], acc[t + 4][2], acc[t][2]);
            sX[r1 * 33 + c0 + 1] = fmaf(acc[t + 4][3], acc[t + 4][3], acc[t][3]);
        }
    }
    // stage MLP weights
    for (int i = tid; i < 1024; i += THREADS) {
        sM[i]        = lin1_w[i];
        sM[1056 + i] = lin2_w[i];
    }
    if (tid < 32) {
        sM[1024 + tid] = lin1_b[tid];
        sM[2080 + tid] = lin2_b[tid];
        sM[2112 + tid] = last_w[tid];
    }
    if (tid == 0) sM[2144] = last_b[0];
    __syncthreads();

    // ---- MLP: 2 threads per row, 16 outputs each ----
    const int row = grow;
    const int hh  = gh;

    float xr[32];
    #pragma unroll
    for (int j = 0; j < 32; ++j) xr[j] = sX[row * 33 + j];
    #pragma unroll
    for (int i = 0; i < 16; ++i) {
        int oi = hh * 16 + i;
        float t = sM[1024 + oi];
        #pragma unroll
        for (int j4 = 0; j4 < 8; ++j4) {
            float4 w = *(const float4*)&sM[oi * 32 + j4 * 4];
            t = fmaf(xr[j4 * 4],     w.x, t);
            t = fmaf(xr[j4 * 4 + 1], w.y, t);
            t = fmaf(xr[j4 * 4 + 2], w.z, t);
            t = fmaf(xr[j4 * 4 + 3], w.w, t);
        }
        sH[row * 33 + oi] = fmaxf(t, 0.f);
    }
    __syncthreads();

    float hr[32];
    #pragma unroll
    for (int j = 0; j < 32; ++j) hr[j] = sH[row * 33 + j];
    #pragma unroll
    for (int i = 0; i < 16; ++i) {
        int oi = hh * 16 + i;
        float t = sM[2080 + oi];
        #pragma unroll
        for (int j4 = 0; j4 < 8; ++j4) {
            float4 w = *(const float4*)&sM[1056 + oi * 32 + j4 * 4];
            t = fmaf(hr[j4 * 4],     w.x, t);
            t = fmaf(hr[j4 * 4 + 1], w.y, t);
            t = fmaf(hr[j4 * 4 + 2], w.z, t);
            t = fmaf(hr[j4 * 4 + 3], w.w, t);
        }
        sX[row * 33 + oi] = fmaxf(t, 0.f);   // reuse sX for h2
    }
    __syncthreads();

    if (hh == 0) {
        float o = sM[2144];
        #pragma unroll
        for (int j = 0; j < 32; ++j) o = fmaf(sX[row * 33 + j], sM[2112 + j], o);
        out[b0 + row] = o;
    }
}

extern "C" void kernel_launch(void* const* d_in, const int* in_sizes, int n_in,
                              void* d_out, int out_size) {
    const int*   Xi     = (const int*)  d_in[0];
    const float* Xv     = (const float*)d_in[1];
    const float* tables = (const float*)d_in[2];
    const float* W1     = (const float*)d_in[3];
    const float* Wi     = (const float*)d_in[4];
    const float* lin1_w = (const float*)d_in[5];
    const float* lin1_b = (const float*)d_in[6];
    const float* lin2_w = (const float*)d_in[7];
    const float* lin2_b = (const float*)d_in[8];
    const float* last_w = (const float*)d_in[9];
    const float* last_b = (const float*)d_in[10];
    float* out = (float*)d_out;

    static bool attr_set = false;
    if (!attr_set) {
        cudaFuncSetAttribute(pnn_kernel, cudaFuncAttributeMaxDynamicSharedMemorySize, SMEM_BYTES);
        attr_set = true;
    }

    prep_kernel<<<(2 * 40 * 8 * 32 * 2 + 255) / 256, 256>>>(W1, Wi);
    pnn_kernel<<<BATCH / ROWSPB, THREADS, SMEM_BYTES>>>(
        Xi, Xv, tables, lin1_w, lin1_b, lin2_w, lin2_b, last_w, last_b, out);
}